// round 11
// baseline (speedup 1.0000x reference)
#include <cuda_runtime.h>
#include <cstdint>

#define L_SEQ 512
#define NB    64
#define HID   1024
#define EMB   512
#define NC    4096   // 4 gates * HID, interleaved col = j*4 + g  (g: 0=i,1=f,2=c,3=o)
#define NCTAS 256    // persistent grid; 2 CTAs/SM -> all resident

typedef unsigned long long ull;

// ---------------- device scratch (no allocs allowed) ----------------
__device__ float g_xproj[(size_t)L_SEQ * NB * NC];     // 512 MB: bias + x-part preacts
__device__ float g_Wr[(size_t)(HID + EMB) * NC];       // 25 MB: interleaved weights
__device__ float g_br[NC];                             // interleaved bias
__device__ float g_h[2 * HID * NB];                    // ping-pong, layout [j][m]
__device__ volatile unsigned g_bar;                    // grid barrier arrival counter

// ---------------- packed fp32x2 helpers (FFMA2 on sm_103a) ----------------
__device__ __forceinline__ ull pk2(float a, float b) {
    ull r; asm("mov.b64 %0, {%1, %2};" : "=l"(r) : "f"(a), "f"(b)); return r;
}
__device__ __forceinline__ void up2(ull v, float& lo, float& hi) {
    asm("mov.b64 {%0, %1}, %2;" : "=f"(lo), "=f"(hi) : "l"(v));
}
__device__ __forceinline__ void fma2(ull& d, ull a, ull b) {
    asm("fma.rn.f32x2 %0, %1, %2, %0;" : "+l"(d) : "l"(a), "l"(b));
}
__device__ __forceinline__ ull add2(ull a, ull b) {
    ull r; asm("add.rn.f32x2 %0, %1, %2;" : "=l"(r) : "l"(a), "l"(b)); return r;
}
__device__ __forceinline__ uint32_t su32(const void* p) {
    return (uint32_t)__cvta_generic_to_shared(p);
}
__device__ __forceinline__ void cpa16(uint32_t d, const float* g) {
    asm volatile("cp.async.cg.shared.global [%0], [%1], 16;" :: "r"(d), "l"(g));
}
#define CP_COMMIT() asm volatile("cp.async.commit_group;" ::: "memory")
#define CP_WAIT0()  asm volatile("cp.async.wait_group 0;" ::: "memory")
#define CP_WAIT1()  asm volatile("cp.async.wait_group 1;" ::: "memory")

// partial-region bank swizzle: c in 0..15, P in 0..31
__device__ __forceinline__ int swz(int c, int P) {
    return (c ^ (P >> 2) ^ ((P & 3) << 2)) & 15;
}

// ---------------- init: zero h0 (ping 0) + barrier counter ----------------
__global__ void k_init() {
    int i = blockIdx.x * blockDim.x + threadIdx.x;
    if (i < HID * NB) g_h[i] = 0.f;
    if (i == 0) g_bar = 0;
}

// ---------------- weight/bias reorg: col = j*4 + g ----------------
__global__ void k_reorg(const float* __restrict__ Wi, const float* __restrict__ bi,
                        const float* __restrict__ Wf, const float* __restrict__ bf,
                        const float* __restrict__ Wc, const float* __restrict__ bc,
                        const float* __restrict__ Wo, const float* __restrict__ bo) {
    int idx = blockIdx.x * 256 + threadIdx.x;
    if (idx < (HID + EMB) * HID) {
        int k = idx >> 10, j = idx & (HID - 1);
        size_t s = (size_t)k * HID + j;
        float4 v = make_float4(Wi[s], Wf[s], Wc[s], Wo[s]);
        *(float4*)&g_Wr[(size_t)k * NC + j * 4] = v;
    }
    if (idx < HID) {
        *(float4*)&g_br[idx * 4] = make_float4(bi[idx], bf[idx], bc[idx], bo[idx]);
    }
}

// ---------------- kernel 1: embedding gather + input projection ----------------
#define BPAD 20
__global__ __launch_bounds__(256) void k_embed_proj(
    const int* __restrict__ x, const float* __restrict__ emb)
{
    __shared__ float a2[16][132];
    __shared__ float bsh[16 * 16 * BPAD];

    int tid = threadIdx.x;
    int jb  = blockIdx.x * 256;
    int by  = blockIdx.y;

    int arow  = tid & 63;
    int ahalf = tid >> 6;
    long tok  = x[by * 64 + arow];
    const float* erow = emb + (size_t)tok * EMB + ahalf * 4;

    int mg = tid >> 4;
    int cg = tid & 15;

    ull acc[32];
    {
        float4 b0 = *(const float4*)(g_br + jb + cg * 16);
        float4 b1 = *(const float4*)(g_br + jb + cg * 16 + 4);
        float4 b2 = *(const float4*)(g_br + jb + cg * 16 + 8);
        float4 b3 = *(const float4*)(g_br + jb + cg * 16 + 12);
        ull p[8] = { pk2(b0.x, b0.y), pk2(b0.z, b0.w), pk2(b1.x, b1.y), pk2(b1.z, b1.w),
                     pk2(b2.x, b2.y), pk2(b2.z, b2.w), pk2(b3.x, b3.y), pk2(b3.z, b3.w) };
#pragma unroll
        for (int m = 0; m < 4; m++)
#pragma unroll
            for (int q = 0; q < 8; q++) acc[m * 8 + q] = p[q];
    }

    float4 va;
    float4 rb[4];
#define E_LOAD(KB)                                                               \
    va = *(const float4*)(erow + (KB));                                         \
    _Pragma("unroll")                                                            \
    for (int i_ = 0; i_ < 4; i_++) {                                             \
        int f_ = tid + i_ * 256; int r_ = f_ >> 6, q_ = f_ & 63;                 \
        rb[i_] = *(const float4*)&g_Wr[(size_t)(HID + (KB) + r_) * NC + jb + q_ * 4]; \
    }

    E_LOAD(0)

    for (int kb = 0; kb < EMB; kb += 16) {
        __syncthreads();
        {
            int k0 = ahalf * 4;
            *(float2*)&a2[k0 + 0][2 * arow] = make_float2(va.x, va.x);
            *(float2*)&a2[k0 + 1][2 * arow] = make_float2(va.y, va.y);
            *(float2*)&a2[k0 + 2][2 * arow] = make_float2(va.z, va.z);
            *(float2*)&a2[k0 + 3][2 * arow] = make_float2(va.w, va.w);
        }
#pragma unroll
        for (int i_ = 0; i_ < 4; i_++) {
            int f_ = tid + i_ * 256; int r_ = f_ >> 6, q_ = f_ & 63;
            *(float4*)&bsh[r_ * (16 * BPAD) + (q_ >> 2) * BPAD + (q_ & 3) * 4] = rb[i_];
        }
        __syncthreads();
        if (kb + 16 < EMB) { E_LOAD(kb + 16) }

        const float* bp = &bsh[cg * BPAD];
#pragma unroll
        for (int k = 0; k < 16; k++) {
            ulonglong2 aa0 = *(const ulonglong2*)&a2[k][8 * mg];
            ulonglong2 aa1 = *(const ulonglong2*)&a2[k][8 * mg + 4];
            ulonglong2 bb0 = *(const ulonglong2*)(bp + k * (16 * BPAD));
            ulonglong2 bb1 = *(const ulonglong2*)(bp + k * (16 * BPAD) + 4);
            ulonglong2 bb2 = *(const ulonglong2*)(bp + k * (16 * BPAD) + 8);
            ulonglong2 bb3 = *(const ulonglong2*)(bp + k * (16 * BPAD) + 12);
            ull am[4] = { aa0.x, aa0.y, aa1.x, aa1.y };
            ull bq[8] = { bb0.x, bb0.y, bb1.x, bb1.y, bb2.x, bb2.y, bb3.x, bb3.y };
#pragma unroll
            for (int m = 0; m < 4; m++)
#pragma unroll
                for (int q = 0; q < 8; q++) fma2(acc[m * 8 + q], am[m], bq[q]);
        }
    }
#undef E_LOAD

#pragma unroll
    for (int m = 0; m < 4; m++) {
        float* op = g_xproj + (size_t)(by * 64 + mg * 4 + m) * NC + jb + cg * 16;
        float l0, h0, l1, h1;
#pragma unroll
        for (int q = 0; q < 4; q++) {
            up2(acc[m * 8 + 2 * q], l0, h0);
            up2(acc[m * 8 + 2 * q + 1], l1, h1);
            *(float4*)(op + q * 4) = make_float4(l0, h0, l1, h1);
        }
    }
}

// ---------------- kernel 2: PERSISTENT LSTM (all 512 steps, one launch) ---------
// 256 CTAs x 256 threads, 2 CTAs/SM (all resident). CTA: 4 hidden units (16 cols),
// W slice 1024x16 = 64 KB persistent smem. 8 warps = 8-way per-warp split-K
// (128 k each), private cp.async double buffers (no block barrier in mainloop).
// Thread tile: 4 m-pairs x 4 cols, natural col-pair packing (u,us,v,vs):
// per k: 3 LDS.128 + 2 swapped-pair builds (4 MOV) + 16 FFMA2.
#define W_FLOATS   16384                  // 1024 x 16
#define STG_FLOATS 8192                   // 8 warps x 2 stages x (8 rows x 64 m)
#define SMEM_LSTM  ((W_FLOATS + STG_FLOATS) * 4)   // 96 KB

__global__ __launch_bounds__(256, 2) void k_lstm(float* __restrict__ out)
{
    extern __shared__ __align__(16) float sm[];
    float* Wsm = sm;                  // [k 0..1023][16 cols]
    float* stg = sm + W_FLOATS;       // per-warp stages; partials alias after loop

    int tid = threadIdx.x;
    int jb  = blockIdx.x * 4;         // hidden units jb..jb+3
    int C0  = jb * 4;                 // interleaved col base (16 cols)

    // ---- load persistent W slice (coalesced: 4096 float4 / 256 threads) ----
#pragma unroll
    for (int i = 0; i < 16; i++) {
        int f = tid + i * 256;        // float4 index 0..4095
        int r = f >> 2, q = f & 3;
        *(float4*)&Wsm[r * 16 + q * 4] =
            *(const float4*)&g_Wr[(size_t)r * NC + C0 + q * 4];
    }

    int lane = tid & 31, wid = tid >> 5;   // wid 0..7 = split-K slice (128 k each)
    int mi = lane >> 2;               // 0..7 -> m-pairs mi*4..+3
    int ci = lane & 3;                // 0..3 -> cols ci*4..+3
    float* stW = stg + wid * 1024;    // 2 stages x 512 floats

    // gate-phase mapping (step-invariant): m fastest for coalesced h writes
    int m  = tid & 63;                // batch row
    int jl = tid >> 6;                // 0..3 -> hidden unit jb+jl
    int P  = m >> 1, e = m & 1;
    int j  = jb + jl;
    float c_reg = 0.f;

    __syncthreads();

#define PFW(DST, SUBBASE) do {                                                   \
    _Pragma("unroll")                                                            \
    for (int j_ = 0; j_ < 4; j_++) {                                             \
        int idx_ = lane + j_ * 32; int r_ = idx_ >> 4, p_ = idx_ & 15;           \
        cpa16(su32((DST) + r_ * 64 + p_ * 4),                                    \
              hp + (size_t)((SUBBASE) + r_) * 64 + p_ * 4);                      \
    }                                                                            \
    CP_COMMIT();                                                                 \
} while (0)

    // xproj preact for step 0 (bias + x-part), prefetched into registers
    float4 xp = *(const float4*)&g_xproj[((size_t)m) * NC + C0 + jl * 4];

    for (int t = 0; t < L_SEQ; t++) {
        const float* hprev = g_h + (size_t)(t & 1) * (HID * NB);
        float*       hnext = g_h + (size_t)((t + 1) & 1) * (HID * NB);
        const float* hp = hprev + (size_t)(wid * 128) * 64;  // this warp's k-rows

        ull acc[16];                  // [p*4 + {u, us, v, vs}]
#pragma unroll
        for (int i = 0; i < 16; i++) acc[i] = 0;

        PFW(stW, 0);
        PFW(stW + 512, 8);

        for (int sub = 0; sub < 16; sub++) {
            if (sub == 15) { CP_WAIT0(); } else { CP_WAIT1(); }
            __syncwarp();
            const float* cur = stW + ((sub & 1) << 9);
            const float* wp  = Wsm + (wid * 128 + sub * 8) * 16 + ci * 4;
#pragma unroll
            for (int kk = 0; kk < 8; kk++) {
                ulonglong2 a0 = *(const ulonglong2*)(cur + kk * 64 + mi * 8);
                ulonglong2 a1 = *(const ulonglong2*)(cur + kk * 64 + mi * 8 + 4);
                float4 bv = *(const float4*)(wp + kk * 16);
                ull u  = pk2(bv.x, bv.y);       // natural pair (reg-aligned, free)
                ull v  = pk2(bv.z, bv.w);       // natural pair (free)
                ull us = pk2(bv.y, bv.x);       // swapped (2 MOV)
                ull vs = pk2(bv.w, bv.z);       // swapped (2 MOV)
                fma2(acc[0],  a0.x, u); fma2(acc[1],  a0.x, us);
                fma2(acc[2],  a0.x, v); fma2(acc[3],  a0.x, vs);
                fma2(acc[4],  a0.y, u); fma2(acc[5],  a0.y, us);
                fma2(acc[6],  a0.y, v); fma2(acc[7],  a0.y, vs);
                fma2(acc[8],  a1.x, u); fma2(acc[9],  a1.x, us);
                fma2(acc[10], a1.x, v); fma2(acc[11], a1.x, vs);
                fma2(acc[12], a1.y, u); fma2(acc[13], a1.y, us);
                fma2(acc[14], a1.y, v); fma2(acc[15], a1.y, vs);
            }
            if (sub < 14) { PFW(stW + ((sub & 1) << 9), (sub + 2) * 8); }
        }

        // ---- split-K partials -> smem, unscrambled to (m_even, m_odd) packing ----
        // acc[p*4+0] (u)  = (me*c0, mo*c1);  acc[p*4+1] (us) = (me*c1, mo*c0)
        // acc[p*4+2] (v)  = (me*c2, mo*c3);  acc[p*4+3] (vs) = (me*c3, mo*c2)
        // R[P][c0] = (me*c0, mo*c0) = (lo(u), hi(us));  R[P][c1] = (lo(us), hi(u))
        // No block sync needed before store: R[wid*512..] aliases exactly this
        // warp's own stages (warp-private; program order suffices).
        ull* R = (ull*)stg;
        {
            int base = wid * 512;
#pragma unroll
            for (int p = 0; p < 4; p++) {
                int Pp = mi * 4 + p;
                int c0 = ci * 4;
                float nl, nh, sl, sh;
                up2(acc[p * 4 + 0], nl, nh); up2(acc[p * 4 + 1], sl, sh);
                R[base + Pp * 16 + swz(c0 + 0, Pp)] = pk2(nl, sh);
                R[base + Pp * 16 + swz(c0 + 1, Pp)] = pk2(sl, nh);
                up2(acc[p * 4 + 2], nl, nh); up2(acc[p * 4 + 3], sl, sh);
                R[base + Pp * 16 + swz(c0 + 2, Pp)] = pk2(nl, sh);
                R[base + Pp * 16 + swz(c0 + 3, Pp)] = pk2(sl, nh);
            }
        }
        __syncthreads();

        // ---- gates: thread -> (m, j); direct 8-slice reduction ----
        float pre[4];
#pragma unroll
        for (int g = 0; g < 4; g++) {
            int c = jl * 4 + g;
            int o = P * 16 + swz(c, P);
            ull s = add2(add2(add2(R[o], R[512 + o]),
                              add2(R[1024 + o], R[1536 + o])),
                         add2(add2(R[2048 + o], R[2560 + o]),
                              add2(R[3072 + o], R[3584 + o])));
            float lo, hi; up2(s, lo, hi);
            pre[g] = e ? hi : lo;
        }
        pre[0] += xp.x; pre[1] += xp.y; pre[2] += xp.z; pre[3] += xp.w;

        float is = 1.f / (1.f + __expf(-pre[0]));
        float fs = 1.f / (1.f + __expf(-pre[1]));
        float gt = tanhf(pre[2]);
        float os = 1.f / (1.f + __expf(-pre[3]));

        float cn = fs * c_reg + is * gt;
        c_reg = cn;
        float hv = os * tanhf(cn);
        hnext[(size_t)j * 64 + m] = hv;                   // coalesced (m across lanes)
        out[((size_t)t * 64 + m) * 1024 + j] = hv;

        // prefetch next step's xproj BEFORE the barrier (latency hidden by spin)
        if (t + 1 < L_SEQ)
            xp = *(const float4*)&g_xproj[((size_t)(t + 1) * 64 + m) * NC + C0 + jl * 4];

        // ---- software grid barrier (all 256 CTAs resident: 2 CTAs/SM) ----
        __threadfence();
        __syncthreads();
        if (tid == 0) {
            atomicAdd((unsigned*)&g_bar, 1u);
            unsigned target = (unsigned)(t + 1) * NCTAS;
            while (g_bar < target) { }
        }
        __syncthreads();
        __threadfence();
    }
#undef PFW
}

// ---------------- launcher ----------------
extern "C" void kernel_launch(void* const* d_in, const int* in_sizes, int n_in,
                              void* d_out, int out_size)
{
    const int*   x   = (const int*)  d_in[0];
    const float* emb = (const float*)d_in[1];
    const float* Wi  = (const float*)d_in[2];
    const float* bi  = (const float*)d_in[3];
    const float* Wf  = (const float*)d_in[4];
    const float* bf  = (const float*)d_in[5];
    const float* Wc  = (const float*)d_in[6];
    const float* bc  = (const float*)d_in[7];
    const float* Wo  = (const float*)d_in[8];
    const float* bo  = (const float*)d_in[9];
    float* out = (float*)d_out;
    (void)in_sizes; (void)n_in; (void)out_size;

    static bool attr_done = false;
    if (!attr_done) {
        cudaFuncSetAttribute(k_lstm, cudaFuncAttributeMaxDynamicSharedMemorySize,
                             SMEM_LSTM);
        attr_done = true;
    }

    k_init<<<(HID * NB + 255) / 256, 256>>>();
    k_reorg<<<((HID + EMB) * HID + 255) / 256, 256>>>(Wi, bi, Wf, bf, Wc, bc, Wo, bo);

    dim3 g1(16, 512);
    k_embed_proj<<<g1, 256>>>(x, emb);

    k_lstm<<<NCTAS, 256, SMEM_LSTM>>>(out);
}

// round 12
// speedup vs baseline: 1.0608x; 1.0608x over previous
#include <cuda_runtime.h>
#include <cstdint>

#define L_SEQ 512
#define NB    64
#define HID   1024
#define EMB   512
#define NC    4096   // 4 gates * HID, interleaved col = j*4 + g  (g: 0=i,1=f,2=c,3=o)
#define NCTAS 256    // persistent grid; 2 CTAs/SM -> all resident

typedef unsigned long long ull;

// ---------------- device scratch (no allocs allowed) ----------------
__device__ float g_xproj[(size_t)L_SEQ * NB * NC];     // 512 MB: bias + x-part preacts
__device__ float g_Wr[(size_t)(HID + EMB) * NC];       // 25 MB: interleaved weights
__device__ float g_br[NC];                             // interleaved bias
__device__ float g_h[2 * HID * NB];                    // ping-pong, layout [j][m]
__device__ unsigned g_bar;                             // grid barrier arrival counter

// ---------------- packed fp32x2 helpers (FFMA2 on sm_103a) ----------------
__device__ __forceinline__ ull pk2(float a, float b) {
    ull r; asm("mov.b64 %0, {%1, %2};" : "=l"(r) : "f"(a), "f"(b)); return r;
}
__device__ __forceinline__ ull dup2(float v) {
    ull r; asm("mov.b64 %0, {%1, %1};" : "=l"(r) : "f"(v)); return r;
}
__device__ __forceinline__ void up2(ull v, float& lo, float& hi) {
    asm("mov.b64 {%0, %1}, %2;" : "=f"(lo), "=f"(hi) : "l"(v));
}
__device__ __forceinline__ void fma2(ull& d, ull a, ull b) {
    asm("fma.rn.f32x2 %0, %1, %2, %0;" : "+l"(d) : "l"(a), "l"(b));
}
__device__ __forceinline__ ull add2(ull a, ull b) {
    ull r; asm("add.rn.f32x2 %0, %1, %2;" : "=l"(r) : "l"(a), "l"(b)); return r;
}
__device__ __forceinline__ uint32_t su32(const void* p) {
    return (uint32_t)__cvta_generic_to_shared(p);
}
__device__ __forceinline__ void cpa16(uint32_t d, const float* g) {
    asm volatile("cp.async.cg.shared.global [%0], [%1], 16;" :: "r"(d), "l"(g));
}
#define CP_COMMIT() asm volatile("cp.async.commit_group;" ::: "memory")
#define CP_WAIT0()  asm volatile("cp.async.wait_group 0;" ::: "memory")
#define CP_WAIT1()  asm volatile("cp.async.wait_group 1;" ::: "memory")

// grid-barrier primitives: release arrive, acquire poll (no L1-flushing membar)
__device__ __forceinline__ void bar_arrive_release(unsigned* p) {
    asm volatile("red.release.gpu.global.add.u32 [%0], %1;" :: "l"(p), "r"(1u)
                 : "memory");
}
__device__ __forceinline__ unsigned ld_acquire(unsigned* p) {
    unsigned v;
    asm volatile("ld.acquire.gpu.global.u32 %0, [%1];" : "=r"(v) : "l"(p) : "memory");
    return v;
}

// partial-region bank swizzle: c in 0..15, P in 0..31
__device__ __forceinline__ int swz(int c, int P) {
    return (c ^ (P >> 2) ^ ((P & 3) << 2)) & 15;
}

// ---------------- init: zero h0 (ping 0) + barrier counter ----------------
__global__ void k_init() {
    int i = blockIdx.x * blockDim.x + threadIdx.x;
    if (i < HID * NB) g_h[i] = 0.f;
    if (i == 0) g_bar = 0;
}

// ---------------- weight/bias reorg: col = j*4 + g ----------------
__global__ void k_reorg(const float* __restrict__ Wi, const float* __restrict__ bi,
                        const float* __restrict__ Wf, const float* __restrict__ bf,
                        const float* __restrict__ Wc, const float* __restrict__ bc,
                        const float* __restrict__ Wo, const float* __restrict__ bo) {
    int idx = blockIdx.x * 256 + threadIdx.x;
    if (idx < (HID + EMB) * HID) {
        int k = idx >> 10, j = idx & (HID - 1);
        size_t s = (size_t)k * HID + j;
        float4 v = make_float4(Wi[s], Wf[s], Wc[s], Wo[s]);
        *(float4*)&g_Wr[(size_t)k * NC + j * 4] = v;
    }
    if (idx < HID) {
        *(float4*)&g_br[idx * 4] = make_float4(bi[idx], bf[idx], bc[idx], bo[idx]);
    }
}

// ---------------- kernel 1: embedding gather + input projection ----------------
#define BPAD 20
__global__ __launch_bounds__(256) void k_embed_proj(
    const int* __restrict__ x, const float* __restrict__ emb)
{
    __shared__ float a2[16][132];
    __shared__ float bsh[16 * 16 * BPAD];

    int tid = threadIdx.x;
    int jb  = blockIdx.x * 256;
    int by  = blockIdx.y;

    int arow  = tid & 63;
    int ahalf = tid >> 6;
    long tok  = x[by * 64 + arow];
    const float* erow = emb + (size_t)tok * EMB + ahalf * 4;

    int mg = tid >> 4;
    int cg = tid & 15;

    ull acc[32];
    {
        float4 b0 = *(const float4*)(g_br + jb + cg * 16);
        float4 b1 = *(const float4*)(g_br + jb + cg * 16 + 4);
        float4 b2 = *(const float4*)(g_br + jb + cg * 16 + 8);
        float4 b3 = *(const float4*)(g_br + jb + cg * 16 + 12);
        ull p[8] = { pk2(b0.x, b0.y), pk2(b0.z, b0.w), pk2(b1.x, b1.y), pk2(b1.z, b1.w),
                     pk2(b2.x, b2.y), pk2(b2.z, b2.w), pk2(b3.x, b3.y), pk2(b3.z, b3.w) };
#pragma unroll
        for (int m = 0; m < 4; m++)
#pragma unroll
            for (int q = 0; q < 8; q++) acc[m * 8 + q] = p[q];
    }

    float4 va;
    float4 rb[4];
#define E_LOAD(KB)                                                               \
    va = *(const float4*)(erow + (KB));                                         \
    _Pragma("unroll")                                                            \
    for (int i_ = 0; i_ < 4; i_++) {                                             \
        int f_ = tid + i_ * 256; int r_ = f_ >> 6, q_ = f_ & 63;                 \
        rb[i_] = *(const float4*)&g_Wr[(size_t)(HID + (KB) + r_) * NC + jb + q_ * 4]; \
    }

    E_LOAD(0)

    for (int kb = 0; kb < EMB; kb += 16) {
        __syncthreads();
        {
            int k0 = ahalf * 4;
            *(float2*)&a2[k0 + 0][2 * arow] = make_float2(va.x, va.x);
            *(float2*)&a2[k0 + 1][2 * arow] = make_float2(va.y, va.y);
            *(float2*)&a2[k0 + 2][2 * arow] = make_float2(va.z, va.z);
            *(float2*)&a2[k0 + 3][2 * arow] = make_float2(va.w, va.w);
        }
#pragma unroll
        for (int i_ = 0; i_ < 4; i_++) {
            int f_ = tid + i_ * 256; int r_ = f_ >> 6, q_ = f_ & 63;
            *(float4*)&bsh[r_ * (16 * BPAD) + (q_ >> 2) * BPAD + (q_ & 3) * 4] = rb[i_];
        }
        __syncthreads();
        if (kb + 16 < EMB) { E_LOAD(kb + 16) }

        const float* bp = &bsh[cg * BPAD];
#pragma unroll
        for (int k = 0; k < 16; k++) {
            ulonglong2 aa0 = *(const ulonglong2*)&a2[k][8 * mg];
            ulonglong2 aa1 = *(const ulonglong2*)&a2[k][8 * mg + 4];
            ulonglong2 bb0 = *(const ulonglong2*)(bp + k * (16 * BPAD));
            ulonglong2 bb1 = *(const ulonglong2*)(bp + k * (16 * BPAD) + 4);
            ulonglong2 bb2 = *(const ulonglong2*)(bp + k * (16 * BPAD) + 8);
            ulonglong2 bb3 = *(const ulonglong2*)(bp + k * (16 * BPAD) + 12);
            ull am[4] = { aa0.x, aa0.y, aa1.x, aa1.y };
            ull bq[8] = { bb0.x, bb0.y, bb1.x, bb1.y, bb2.x, bb2.y, bb3.x, bb3.y };
#pragma unroll
            for (int m = 0; m < 4; m++)
#pragma unroll
                for (int q = 0; q < 8; q++) fma2(acc[m * 8 + q], am[m], bq[q]);
        }
    }
#undef E_LOAD

#pragma unroll
    for (int m = 0; m < 4; m++) {
        float* op = g_xproj + (size_t)(by * 64 + mg * 4 + m) * NC + jb + cg * 16;
        float l0, h0, l1, h1;
#pragma unroll
        for (int q = 0; q < 4; q++) {
            up2(acc[m * 8 + 2 * q], l0, h0);
            up2(acc[m * 8 + 2 * q + 1], l1, h1);
            *(float4*)(op + q * 4) = make_float4(l0, h0, l1, h1);
        }
    }
}

// ---------------- kernel 2: PERSISTENT LSTM (all 512 steps, one launch) ---------
// 256 CTAs x 256 threads, 2 CTAs/SM (all resident). CTA: 4 hidden units (16 cols),
// W slice 1024x16 = 64 KB persistent smem. 8 warps = 8-way per-warp split-K
// (128 k each), private cp.async double buffers (no block barrier in mainloop).
// Thread tile: 4 m-pairs x 4 cols = 16 packed accs; per k: 3 LDS.128 + 16 FFMA2.
#define W_FLOATS   16384                  // 1024 x 16
#define STG_FLOATS 8192                   // 8 warps x 2 stages x (8 rows x 64 m)
#define SMEM_LSTM  ((W_FLOATS + STG_FLOATS) * 4)   // 96 KB

__global__ __launch_bounds__(256, 2) void k_lstm(float* __restrict__ out)
{
    extern __shared__ __align__(16) float sm[];
    float* Wsm = sm;                  // [k 0..1023][16 cols]
    float* stg = sm + W_FLOATS;       // per-warp stages; partials alias after loop

    int tid = threadIdx.x;
    int jb  = blockIdx.x * 4;         // hidden units jb..jb+3
    int C0  = jb * 4;                 // interleaved col base (16 cols)

    // ---- load persistent W slice (coalesced: 4096 float4 / 256 threads) ----
#pragma unroll
    for (int i = 0; i < 16; i++) {
        int f = tid + i * 256;        // float4 index 0..4095
        int r = f >> 2, q = f & 3;
        *(float4*)&Wsm[r * 16 + q * 4] =
            *(const float4*)&g_Wr[(size_t)r * NC + C0 + q * 4];
    }

    int lane = tid & 31, wid = tid >> 5;   // wid 0..7 = split-K slice (128 k each)
    int mi = lane >> 2;               // 0..7 -> m-pairs mi*4..+3
    int ci = lane & 3;                // 0..3 -> cols ci*4..+3
    float* stW = stg + wid * 1024;    // 2 stages x 512 floats

    // gate-phase mapping (step-invariant): m fastest for coalesced h writes
    int m  = tid & 63;                // batch row
    int jl = tid >> 6;                // 0..3 -> hidden unit jb+jl
    int P  = m >> 1, e = m & 1;
    int j  = jb + jl;
    float c_reg = 0.f;

    __syncthreads();

#define PFW(DST, SUBBASE) do {                                                   \
    _Pragma("unroll")                                                            \
    for (int j_ = 0; j_ < 4; j_++) {                                             \
        int idx_ = lane + j_ * 32; int r_ = idx_ >> 4, p_ = idx_ & 15;           \
        cpa16(su32((DST) + r_ * 64 + p_ * 4),                                    \
              hp + (size_t)((SUBBASE) + r_) * 64 + p_ * 4);                      \
    }                                                                            \
    CP_COMMIT();                                                                 \
} while (0)

    // xproj preact for step 0 (bias + x-part), prefetched into registers
    float4 xp = *(const float4*)&g_xproj[((size_t)m) * NC + C0 + jl * 4];

    for (int t = 0; t < L_SEQ; t++) {
        const float* hprev = g_h + (size_t)(t & 1) * (HID * NB);
        float*       hnext = g_h + (size_t)((t + 1) & 1) * (HID * NB);
        const float* hp = hprev + (size_t)(wid * 128) * 64;  // this warp's k-rows

        ull acc[16];
#pragma unroll
        for (int i = 0; i < 16; i++) acc[i] = 0;

        PFW(stW, 0);
        PFW(stW + 512, 8);

        for (int sub = 0; sub < 16; sub++) {
            if (sub == 15) { CP_WAIT0(); } else { CP_WAIT1(); }
            __syncwarp();
            const float* cur = stW + ((sub & 1) << 9);
            const float* wp  = Wsm + (wid * 128 + sub * 8) * 16 + ci * 4;
#pragma unroll
            for (int kk = 0; kk < 8; kk++) {
                ulonglong2 a0 = *(const ulonglong2*)(cur + kk * 64 + mi * 8);
                ulonglong2 a1 = *(const ulonglong2*)(cur + kk * 64 + mi * 8 + 4);
                float4 bv = *(const float4*)(wp + kk * 16);
                ull d0 = dup2(bv.x), d1 = dup2(bv.y), d2 = dup2(bv.z), d3 = dup2(bv.w);
                fma2(acc[0],  a0.x, d0); fma2(acc[1],  a0.x, d1);
                fma2(acc[2],  a0.x, d2); fma2(acc[3],  a0.x, d3);
                fma2(acc[4],  a0.y, d0); fma2(acc[5],  a0.y, d1);
                fma2(acc[6],  a0.y, d2); fma2(acc[7],  a0.y, d3);
                fma2(acc[8],  a1.x, d0); fma2(acc[9],  a1.x, d1);
                fma2(acc[10], a1.x, d2); fma2(acc[11], a1.x, d3);
                fma2(acc[12], a1.y, d0); fma2(acc[13], a1.y, d1);
                fma2(acc[14], a1.y, d2); fma2(acc[15], a1.y, d3);
            }
            if (sub < 14) { PFW(stW + ((sub & 1) << 9), (sub + 2) * 8); }
        }

        // ---- split-K partials -> smem (warp-private region: aliases this warp's
        // own stages, so NO block sync needed before the store; program order ok) --
        ull* R = (ull*)stg;
        {
            int base = wid * 512;
#pragma unroll
            for (int p = 0; p < 4; p++) {
                int Pp = mi * 4 + p;
#pragma unroll
                for (int cc = 0; cc < 4; cc++) {
                    int c = ci * 4 + cc;
                    R[base + Pp * 16 + swz(c, Pp)] = acc[p * 4 + cc];
                }
            }
        }
        __syncthreads();

        // ---- gates: thread -> (m, j); direct 8-slice reduction ----
        float pre[4];
#pragma unroll
        for (int g = 0; g < 4; g++) {
            int c = jl * 4 + g;
            int o = P * 16 + swz(c, P);
            ull s = add2(add2(add2(R[o], R[512 + o]),
                              add2(R[1024 + o], R[1536 + o])),
                         add2(add2(R[2048 + o], R[2560 + o]),
                              add2(R[3072 + o], R[3584 + o])));
            float lo, hi; up2(s, lo, hi);
            pre[g] = e ? hi : lo;
        }
        pre[0] += xp.x; pre[1] += xp.y; pre[2] += xp.z; pre[3] += xp.w;

        float is = 1.f / (1.f + __expf(-pre[0]));
        float fs = 1.f / (1.f + __expf(-pre[1]));
        float gt = tanhf(pre[2]);
        float os = 1.f / (1.f + __expf(-pre[3]));

        float cn = fs * c_reg + is * gt;
        c_reg = cn;
        float hv = os * tanhf(cn);
        hnext[(size_t)j * 64 + m] = hv;                   // coalesced (m across lanes)
        out[((size_t)t * 64 + m) * 1024 + j] = hv;

        // prefetch next step's xproj BEFORE the barrier (latency hidden by spin)
        if (t + 1 < L_SEQ)
            xp = *(const float4*)&g_xproj[((size_t)(t + 1) * 64 + m) * NC + C0 + jl * 4];

        // ---- software grid barrier: release arrive + acquire poll ----
        // bar.sync orders this CTA's h-writes before tid0's release (cumulative);
        // acquire + bar.sync on the observer side publishes them. No L1-flushing
        // gpu membar needed. All 256 CTAs resident (2/SM) -> no deadlock.
        __syncthreads();
        if (tid == 0) {
            bar_arrive_release(&g_bar);
            unsigned target = (unsigned)(t + 1) * NCTAS;
            while (ld_acquire(&g_bar) < target) { }
        }
        __syncthreads();
    }
#undef PFW
}

// ---------------- launcher ----------------
extern "C" void kernel_launch(void* const* d_in, const int* in_sizes, int n_in,
                              void* d_out, int out_size)
{
    const int*   x   = (const int*)  d_in[0];
    const float* emb = (const float*)d_in[1];
    const float* Wi  = (const float*)d_in[2];
    const float* bi  = (const float*)d_in[3];
    const float* Wf  = (const float*)d_in[4];
    const float* bf  = (const float*)d_in[5];
    const float* Wc  = (const float*)d_in[6];
    const float* bc  = (const float*)d_in[7];
    const float* Wo  = (const float*)d_in[8];
    const float* bo  = (const float*)d_in[9];
    float* out = (float*)d_out;
    (void)in_sizes; (void)n_in; (void)out_size;

    static bool attr_done = false;
    if (!attr_done) {
        cudaFuncSetAttribute(k_lstm, cudaFuncAttributeMaxDynamicSharedMemorySize,
                             SMEM_LSTM);
        attr_done = true;
    }

    k_init<<<(HID * NB + 255) / 256, 256>>>();
    k_reorg<<<((HID + EMB) * HID + 255) / 256, 256>>>(Wi, bi, Wf, bf, Wc, bc, Wo, bo);

    dim3 g1(16, 512);
    k_embed_proj<<<g1, 256>>>(x, emb);

    k_lstm<<<NCTAS, 256, SMEM_LSTM>>>(out);
}

// round 13
// speedup vs baseline: 1.0646x; 1.0036x over previous
#include <cuda_runtime.h>
#include <cstdint>

#define L_SEQ 512
#define NB    64
#define HID   1024
#define EMB   512
#define NC    4096   // 4 gates * HID, interleaved col = j*4 + g  (g: 0=i,1=f,2=c,3=o)
#define NCTAS 256    // persistent grid; 2 CTAs/SM -> all resident

typedef unsigned long long ull;

// ---------------- device scratch (no allocs allowed) ----------------
__device__ float g_xproj[(size_t)L_SEQ * NB * NC];     // 512 MB: bias + x-part preacts
__device__ float g_Wr[(size_t)(HID + EMB) * NC];       // 25 MB: interleaved weights
__device__ float g_br[NC];                             // interleaved bias
__device__ float g_h[2 * HID * NB];                    // ping-pong, layout [j][m]
__device__ unsigned g_bar;                             // grid barrier arrival counter

// ---------------- packed fp32x2 helpers (FFMA2 on sm_103a) ----------------
__device__ __forceinline__ ull pk2(float a, float b) {
    ull r; asm("mov.b64 %0, {%1, %2};" : "=l"(r) : "f"(a), "f"(b)); return r;
}
__device__ __forceinline__ ull dup2(float v) {
    ull r; asm("mov.b64 %0, {%1, %1};" : "=l"(r) : "f"(v)); return r;
}
__device__ __forceinline__ void up2(ull v, float& lo, float& hi) {
    asm("mov.b64 {%0, %1}, %2;" : "=f"(lo), "=f"(hi) : "l"(v));
}
__device__ __forceinline__ void fma2(ull& d, ull a, ull b) {
    asm("fma.rn.f32x2 %0, %1, %2, %0;" : "+l"(d) : "l"(a), "l"(b));
}
__device__ __forceinline__ ull add2(ull a, ull b) {
    ull r; asm("add.rn.f32x2 %0, %1, %2;" : "=l"(r) : "l"(a), "l"(b)); return r;
}
__device__ __forceinline__ uint32_t su32(const void* p) {
    return (uint32_t)__cvta_generic_to_shared(p);
}
__device__ __forceinline__ void cpa16(uint32_t d, const float* g) {
    asm volatile("cp.async.cg.shared.global [%0], [%1], 16;" :: "r"(d), "l"(g));
}
#define CP_COMMIT() asm volatile("cp.async.commit_group;" ::: "memory")
#define CP_WAIT0()  asm volatile("cp.async.wait_group 0;" ::: "memory")
#define CP_WAIT1()  asm volatile("cp.async.wait_group 1;" ::: "memory")
#define CP_WAIT2()  asm volatile("cp.async.wait_group 2;" ::: "memory")

// grid-barrier primitives: release arrive, acquire poll (no L1-flushing membar)
__device__ __forceinline__ void bar_arrive_release(unsigned* p) {
    asm volatile("red.release.gpu.global.add.u32 [%0], %1;" :: "l"(p), "r"(1u)
                 : "memory");
}
__device__ __forceinline__ unsigned ld_acquire(unsigned* p) {
    unsigned v;
    asm volatile("ld.acquire.gpu.global.u32 %0, [%1];" : "=r"(v) : "l"(p) : "memory");
    return v;
}

// cheap gates: MUFU-based (__expf, __fdividef); error ~few ulp, << 1e-3 budget
__device__ __forceinline__ float sigm_f(float v) {
    return __fdividef(1.f, 1.f + __expf(-v));
}
__device__ __forceinline__ float tanh_f(float v) {
    return 1.f - __fdividef(2.f, __expf(2.f * v) + 1.f);
}

// partial-region bank swizzle: c in 0..15, P in 0..31
__device__ __forceinline__ int swz(int c, int P) {
    return (c ^ (P >> 2) ^ ((P & 3) << 2)) & 15;
}

// ---------------- init: zero h0 (ping 0) + barrier counter ----------------
__global__ void k_init() {
    int i = blockIdx.x * blockDim.x + threadIdx.x;
    if (i < HID * NB) g_h[i] = 0.f;
    if (i == 0) g_bar = 0;
}

// ---------------- weight/bias reorg: col = j*4 + g ----------------
__global__ void k_reorg(const float* __restrict__ Wi, const float* __restrict__ bi,
                        const float* __restrict__ Wf, const float* __restrict__ bf,
                        const float* __restrict__ Wc, const float* __restrict__ bc,
                        const float* __restrict__ Wo, const float* __restrict__ bo) {
    int idx = blockIdx.x * 256 + threadIdx.x;
    if (idx < (HID + EMB) * HID) {
        int k = idx >> 10, j = idx & (HID - 1);
        size_t s = (size_t)k * HID + j;
        float4 v = make_float4(Wi[s], Wf[s], Wc[s], Wo[s]);
        *(float4*)&g_Wr[(size_t)k * NC + j * 4] = v;
    }
    if (idx < HID) {
        *(float4*)&g_br[idx * 4] = make_float4(bi[idx], bf[idx], bc[idx], bo[idx]);
    }
}

// ---------------- kernel 1: embedding gather + input projection ----------------
#define BPAD 20
__global__ __launch_bounds__(256) void k_embed_proj(
    const int* __restrict__ x, const float* __restrict__ emb)
{
    __shared__ float a2[16][132];
    __shared__ float bsh[16 * 16 * BPAD];

    int tid = threadIdx.x;
    int jb  = blockIdx.x * 256;
    int by  = blockIdx.y;

    int arow  = tid & 63;
    int ahalf = tid >> 6;
    long tok  = x[by * 64 + arow];
    const float* erow = emb + (size_t)tok * EMB + ahalf * 4;

    int mg = tid >> 4;
    int cg = tid & 15;

    ull acc[32];
    {
        float4 b0 = *(const float4*)(g_br + jb + cg * 16);
        float4 b1 = *(const float4*)(g_br + jb + cg * 16 + 4);
        float4 b2 = *(const float4*)(g_br + jb + cg * 16 + 8);
        float4 b3 = *(const float4*)(g_br + jb + cg * 16 + 12);
        ull p[8] = { pk2(b0.x, b0.y), pk2(b0.z, b0.w), pk2(b1.x, b1.y), pk2(b1.z, b1.w),
                     pk2(b2.x, b2.y), pk2(b2.z, b2.w), pk2(b3.x, b3.y), pk2(b3.z, b3.w) };
#pragma unroll
        for (int m = 0; m < 4; m++)
#pragma unroll
            for (int q = 0; q < 8; q++) acc[m * 8 + q] = p[q];
    }

    float4 va;
    float4 rb[4];
#define E_LOAD(KB)                                                               \
    va = *(const float4*)(erow + (KB));                                         \
    _Pragma("unroll")                                                            \
    for (int i_ = 0; i_ < 4; i_++) {                                             \
        int f_ = tid + i_ * 256; int r_ = f_ >> 6, q_ = f_ & 63;                 \
        rb[i_] = *(const float4*)&g_Wr[(size_t)(HID + (KB) + r_) * NC + jb + q_ * 4]; \
    }

    E_LOAD(0)

    for (int kb = 0; kb < EMB; kb += 16) {
        __syncthreads();
        {
            int k0 = ahalf * 4;
            *(float2*)&a2[k0 + 0][2 * arow] = make_float2(va.x, va.x);
            *(float2*)&a2[k0 + 1][2 * arow] = make_float2(va.y, va.y);
            *(float2*)&a2[k0 + 2][2 * arow] = make_float2(va.z, va.z);
            *(float2*)&a2[k0 + 3][2 * arow] = make_float2(va.w, va.w);
        }
#pragma unroll
        for (int i_ = 0; i_ < 4; i_++) {
            int f_ = tid + i_ * 256; int r_ = f_ >> 6, q_ = f_ & 63;
            *(float4*)&bsh[r_ * (16 * BPAD) + (q_ >> 2) * BPAD + (q_ & 3) * 4] = rb[i_];
        }
        __syncthreads();
        if (kb + 16 < EMB) { E_LOAD(kb + 16) }

        const float* bp = &bsh[cg * BPAD];
#pragma unroll
        for (int k = 0; k < 16; k++) {
            ulonglong2 aa0 = *(const ulonglong2*)&a2[k][8 * mg];
            ulonglong2 aa1 = *(const ulonglong2*)&a2[k][8 * mg + 4];
            ulonglong2 bb0 = *(const ulonglong2*)(bp + k * (16 * BPAD));
            ulonglong2 bb1 = *(const ulonglong2*)(bp + k * (16 * BPAD) + 4);
            ulonglong2 bb2 = *(const ulonglong2*)(bp + k * (16 * BPAD) + 8);
            ulonglong2 bb3 = *(const ulonglong2*)(bp + k * (16 * BPAD) + 12);
            ull am[4] = { aa0.x, aa0.y, aa1.x, aa1.y };
            ull bq[8] = { bb0.x, bb0.y, bb1.x, bb1.y, bb2.x, bb2.y, bb3.x, bb3.y };
#pragma unroll
            for (int m = 0; m < 4; m++)
#pragma unroll
                for (int q = 0; q < 8; q++) fma2(acc[m * 8 + q], am[m], bq[q]);
        }
    }
#undef E_LOAD

#pragma unroll
    for (int m = 0; m < 4; m++) {
        float* op = g_xproj + (size_t)(by * 64 + mg * 4 + m) * NC + jb + cg * 16;
        float l0, h0, l1, h1;
#pragma unroll
        for (int q = 0; q < 4; q++) {
            up2(acc[m * 8 + 2 * q], l0, h0);
            up2(acc[m * 8 + 2 * q + 1], l1, h1);
            *(float4*)(op + q * 4) = make_float4(l0, h0, l1, h1);
        }
    }
}

// ---------------- kernel 2: PERSISTENT LSTM (all 512 steps, one launch) ---------
// 256 CTAs x 256 threads, 2 CTAs/SM (all resident). CTA: 4 hidden units (16 cols),
// W slice 1024x16 = 64 KB persistent smem. 8 warps = 8-way per-warp split-K
// (128 k each), private cp.async TRIPLE buffers (no block barrier in mainloop).
// Thread tile: 4 m-pairs x 4 cols = 16 packed accs; per k: 3 LDS.128 + 16 FFMA2.
#define W_FLOATS   16384                  // 1024 x 16
#define STG_FLOATS (8 * 1536)             // 8 warps x 3 stages x (8 rows x 64 m)
#define SMEM_LSTM  ((W_FLOATS + STG_FLOATS) * 4)   // 112 KB (2 CTAs/SM: 224<=228)

__global__ __launch_bounds__(256, 2) void k_lstm(float* __restrict__ out)
{
    extern __shared__ __align__(16) float sm[];
    float* Wsm = sm;                  // [k 0..1023][16 cols]
    float* stg = sm + W_FLOATS;       // per-warp stages; partials alias own region

    int tid = threadIdx.x;
    int jb  = blockIdx.x * 4;         // hidden units jb..jb+3
    int C0  = jb * 4;                 // interleaved col base (16 cols)

    // ---- load persistent W slice (coalesced: 4096 float4 / 256 threads) ----
#pragma unroll
    for (int i = 0; i < 16; i++) {
        int f = tid + i * 256;        // float4 index 0..4095
        int r = f >> 2, q = f & 3;
        *(float4*)&Wsm[r * 16 + q * 4] =
            *(const float4*)&g_Wr[(size_t)r * NC + C0 + q * 4];
    }

    int lane = tid & 31, wid = tid >> 5;   // wid 0..7 = split-K slice (128 k each)
    int mi = lane >> 2;               // 0..7 -> m-pairs mi*4..+3
    int ci = lane & 3;                // 0..3 -> cols ci*4..+3
    float* stW = stg + wid * 1536;    // 3 stages x 512 floats (warp-private)

    // gate-phase mapping (step-invariant): m fastest for coalesced h writes
    int m  = tid & 63;                // batch row
    int jl = tid >> 6;                // 0..3 -> hidden unit jb+jl
    int P  = m >> 1, e = m & 1;
    int j  = jb + jl;
    float c_reg = 0.f;

    __syncthreads();

#define PFW(DST, SUBBASE) do {                                                   \
    _Pragma("unroll")                                                            \
    for (int j_ = 0; j_ < 4; j_++) {                                             \
        int idx_ = lane + j_ * 32; int r_ = idx_ >> 4, p_ = idx_ & 15;           \
        cpa16(su32((DST) + r_ * 64 + p_ * 4),                                    \
              hp + (size_t)((SUBBASE) + r_) * 64 + p_ * 4);                      \
    }                                                                            \
    CP_COMMIT();                                                                 \
} while (0)

    // xproj preact for step 0 (bias + x-part), prefetched into registers
    float4 xp = *(const float4*)&g_xproj[((size_t)m) * NC + C0 + jl * 4];

    for (int t = 0; t < L_SEQ; t++) {
        const float* hprev = g_h + (size_t)(t & 1) * (HID * NB);
        float*       hnext = g_h + (size_t)((t + 1) & 1) * (HID * NB);
        const float* hp = hprev + (size_t)(wid * 128) * 64;  // this warp's k-rows

        ull acc[16];
#pragma unroll
        for (int i = 0; i < 16; i++) acc[i] = 0;

        PFW(stW, 0);
        PFW(stW + 512, 8);
        PFW(stW + 1024, 16);

        int sidx = 0;                 // sub % 3 (avoid div in loop)
        for (int sub = 0; sub < 16; sub++) {
            if (sub <= 13) { CP_WAIT2(); }
            else if (sub == 14) { CP_WAIT1(); }
            else { CP_WAIT0(); }
            __syncwarp();
            float* cur = stW + (sidx << 9);
            const float* wp = Wsm + (wid * 128 + sub * 8) * 16 + ci * 4;
#pragma unroll
            for (int kk = 0; kk < 8; kk++) {
                ulonglong2 a0 = *(const ulonglong2*)(cur + kk * 64 + mi * 8);
                ulonglong2 a1 = *(const ulonglong2*)(cur + kk * 64 + mi * 8 + 4);
                float4 bv = *(const float4*)(wp + kk * 16);
                ull d0 = dup2(bv.x), d1 = dup2(bv.y), d2 = dup2(bv.z), d3 = dup2(bv.w);
                fma2(acc[0],  a0.x, d0); fma2(acc[1],  a0.x, d1);
                fma2(acc[2],  a0.x, d2); fma2(acc[3],  a0.x, d3);
                fma2(acc[4],  a0.y, d0); fma2(acc[5],  a0.y, d1);
                fma2(acc[6],  a0.y, d2); fma2(acc[7],  a0.y, d3);
                fma2(acc[8],  a1.x, d0); fma2(acc[9],  a1.x, d1);
                fma2(acc[10], a1.x, d2); fma2(acc[11], a1.x, d3);
                fma2(acc[12], a1.y, d0); fma2(acc[13], a1.y, d1);
                fma2(acc[14], a1.y, d2); fma2(acc[15], a1.y, d3);
            }
            if (sub < 13) { PFW(cur, (sub + 3) * 8); }   // refill just-consumed stage
            sidx = (sidx == 2) ? 0 : sidx + 1;
        }

        // ---- split-K partials -> smem (aliases THIS warp's own stage region:
        // 512 ull = 4096 B <= 6144 B; warp-private -> no block sync before store) --
        ull* Rw = (ull*)stW;
        {
#pragma unroll
            for (int p = 0; p < 4; p++) {
                int Pp = mi * 4 + p;
#pragma unroll
                for (int cc = 0; cc < 4; cc++) {
                    int c = ci * 4 + cc;
                    Rw[Pp * 16 + swz(c, Pp)] = acc[p * 4 + cc];
                }
            }
        }
        __syncthreads();

        // ---- gates: thread -> (m, j); direct 8-slice reduction ----
        ull* R = (ull*)stg;           // slice w at ull offset w*768
        float pre[4];
#pragma unroll
        for (int g = 0; g < 4; g++) {
            int c = jl * 4 + g;
            int o = P * 16 + swz(c, P);
            ull s = add2(add2(add2(R[o], R[768 + o]),
                              add2(R[1536 + o], R[2304 + o])),
                         add2(add2(R[3072 + o], R[3840 + o]),
                              add2(R[4608 + o], R[5376 + o])));
            float lo, hi; up2(s, lo, hi);
            pre[g] = e ? hi : lo;
        }
        pre[0] += xp.x; pre[1] += xp.y; pre[2] += xp.z; pre[3] += xp.w;

        float is = sigm_f(pre[0]);
        float fs = sigm_f(pre[1]);
        float gt = tanh_f(pre[2]);
        float os = sigm_f(pre[3]);

        float cn = fs * c_reg + is * gt;
        c_reg = cn;
        float hv = os * tanh_f(cn);
        hnext[(size_t)j * 64 + m] = hv;                   // coalesced (m across lanes)
        out[((size_t)t * 64 + m) * 1024 + j] = hv;

        // prefetch next step's xproj BEFORE the barrier (latency hidden by spin)
        if (t + 1 < L_SEQ)
            xp = *(const float4*)&g_xproj[((size_t)(t + 1) * 64 + m) * NC + C0 + jl * 4];

        // ---- software grid barrier: release arrive + acquire poll ----
        __syncthreads();
        if (tid == 0) {
            bar_arrive_release(&g_bar);
            unsigned target = (unsigned)(t + 1) * NCTAS;
            while (ld_acquire(&g_bar) < target) { }
        }
        __syncthreads();
    }
#undef PFW
}

// ---------------- launcher ----------------
extern "C" void kernel_launch(void* const* d_in, const int* in_sizes, int n_in,
                              void* d_out, int out_size)
{
    const int*   x   = (const int*)  d_in[0];
    const float* emb = (const float*)d_in[1];
    const float* Wi  = (const float*)d_in[2];
    const float* bi  = (const float*)d_in[3];
    const float* Wf  = (const float*)d_in[4];
    const float* bf  = (const float*)d_in[5];
    const float* Wc  = (const float*)d_in[6];
    const float* bc  = (const float*)d_in[7];
    const float* Wo  = (const float*)d_in[8];
    const float* bo  = (const float*)d_in[9];
    float* out = (float*)d_out;
    (void)in_sizes; (void)n_in; (void)out_size;

    static bool attr_done = false;
    if (!attr_done) {
        cudaFuncSetAttribute(k_lstm, cudaFuncAttributeMaxDynamicSharedMemorySize,
                             SMEM_LSTM);
        attr_done = true;
    }

    k_init<<<(HID * NB + 255) / 256, 256>>>();
    k_reorg<<<((HID + EMB) * HID + 255) / 256, 256>>>(Wi, bi, Wf, bf, Wc, bc, Wo, bo);

    dim3 g1(16, 512);
    k_embed_proj<<<g1, 256>>>(x, emb);

    k_lstm<<<NCTAS, 256, SMEM_LSTM>>>(out);
}

// round 15
// speedup vs baseline: 1.1784x; 1.1069x over previous
#include <cuda_runtime.h>
#include <cuda_bf16.h>
#include <cstdint>

#define L_SEQ 512
#define NB    64
#define HID   1024
#define EMB   512
#define NC    4096   // 4 gates * HID, interleaved col = j*4 + g  (g: 0=i,1=f,2=c,3=o)
#define NCTAS 128    // persistent grid; 1 CTA/SM -> all resident

typedef unsigned long long ull;

// ---------------- device scratch (no allocs allowed) ----------------
__device__ float g_xproj[(size_t)L_SEQ * NB * NC];       // bias + x-part preacts
__device__ float g_Wr[(size_t)(HID + EMB) * NC];         // interleaved fp32 W (embed)
__device__ float g_br[NC];                               // interleaved bias
__device__ __nv_bfloat16 g_WT[2][NC][HID];               // [split][col][k] recurrent W
__device__ __nv_bfloat16 g_hbf[2][2][NB][HID];           // [ping][split][m][k]
__device__ unsigned g_bar;                               // grid barrier counter

// ---------------- packed fp32x2 helpers (embed kernel) ----------------
__device__ __forceinline__ ull pk2(float a, float b) {
    ull r; asm("mov.b64 %0, {%1, %2};" : "=l"(r) : "f"(a), "f"(b)); return r;
}
__device__ __forceinline__ void up2(ull v, float& lo, float& hi) {
    asm("mov.b64 {%0, %1}, %2;" : "=f"(lo), "=f"(hi) : "l"(v));
}
__device__ __forceinline__ void fma2(ull& d, ull a, ull b) {
    asm("fma.rn.f32x2 %0, %1, %2, %0;" : "+l"(d) : "l"(a), "l"(b));
}

// ---------------- misc helpers ----------------
__device__ __forceinline__ uint32_t su32(const void* p) {
    return (uint32_t)__cvta_generic_to_shared(p);
}
__device__ __forceinline__ void cpa16(uint32_t d, const void* g) {
    asm volatile("cp.async.cg.shared.global [%0], [%1], 16;" :: "r"(d), "l"(g));
}
#define CP_COMMIT() asm volatile("cp.async.commit_group;" ::: "memory")
#define CP_WAIT0()  asm volatile("cp.async.wait_group 0;" ::: "memory")

__device__ __forceinline__ void bar_arrive_release(unsigned* p) {
    asm volatile("red.release.gpu.global.add.u32 [%0], %1;" :: "l"(p), "r"(1u)
                 : "memory");
}
__device__ __forceinline__ unsigned ld_acquire(unsigned* p) {
    unsigned v;
    asm volatile("ld.acquire.gpu.global.u32 %0, [%1];" : "=r"(v) : "l"(p) : "memory");
    return v;
}
__device__ __forceinline__ float sigm_f(float v) {
    return __fdividef(1.f, 1.f + __expf(-v));
}
__device__ __forceinline__ float tanh_f(float v) {
    return 1.f - __fdividef(2.f, __expf(2.f * v) + 1.f);
}

// ---------------- tensor-core primitives (portable sm_80 path) ----------------
__device__ __forceinline__ void ldsm_x4(unsigned* r, uint32_t addr) {
    asm volatile("ldmatrix.sync.aligned.m8n8.x4.shared.b16 {%0,%1,%2,%3}, [%4];"
        : "=r"(r[0]), "=r"(r[1]), "=r"(r[2]), "=r"(r[3]) : "r"(addr));
}
__device__ __forceinline__ void ldsm_x2(unsigned* r, uint32_t addr) {
    asm volatile("ldmatrix.sync.aligned.m8n8.x2.shared.b16 {%0,%1}, [%2];"
        : "=r"(r[0]), "=r"(r[1]) : "r"(addr));
}
__device__ __forceinline__ void mma_bf16(float* d, const unsigned* a,
                                         const unsigned* b) {
    asm volatile(
        "mma.sync.aligned.m16n8k16.row.col.f32.bf16.bf16.f32 "
        "{%0,%1,%2,%3}, {%4,%5,%6,%7}, {%8,%9}, {%0,%1,%2,%3};"
        : "+f"(d[0]), "+f"(d[1]), "+f"(d[2]), "+f"(d[3])
        : "r"(a[0]), "r"(a[1]), "r"(a[2]), "r"(a[3]), "r"(b[0]), "r"(b[1]));
}

// ---------------- init: zero h0 bf16 planes + barrier counter ----------------
__global__ void k_init() {
    int i = blockIdx.x * blockDim.x + threadIdx.x;   // 65536 threads
    unsigned* hb = (unsigned*)g_hbf;                 // 131072 uints total
    hb[i] = 0u; hb[i + 65536] = 0u;
    if (i == 0) g_bar = 0;
}

// ---------------- weight/bias reorg: fp32 interleaved + bf16 hi/lo transposed ----
__global__ void k_reorg(const float* __restrict__ Wi, const float* __restrict__ bi,
                        const float* __restrict__ Wf, const float* __restrict__ bf,
                        const float* __restrict__ Wc, const float* __restrict__ bc,
                        const float* __restrict__ Wo, const float* __restrict__ bo) {
    int idx = blockIdx.x * 256 + threadIdx.x;
    if (idx < (HID + EMB) * HID) {
        int k = idx >> 10, j = idx & (HID - 1);
        size_t s = (size_t)k * HID + j;
        float4 v = make_float4(Wi[s], Wf[s], Wc[s], Wo[s]);
        *(float4*)&g_Wr[(size_t)k * NC + j * 4] = v;
        if (k < HID) {     // recurrent part -> bf16 hi/lo, [col][k]
            float vv[4] = { v.x, v.y, v.z, v.w };
#pragma unroll
            for (int g = 0; g < 4; g++) {
                int col = j * 4 + g;
                __nv_bfloat16 hi = __float2bfloat16(vv[g]);
                __nv_bfloat16 lo = __float2bfloat16(vv[g] - __bfloat162float(hi));
                g_WT[0][col][k] = hi;
                g_WT[1][col][k] = lo;
            }
        }
    }
    if (idx < HID) {
        *(float4*)&g_br[idx * 4] = make_float4(bi[idx], bf[idx], bc[idx], bo[idx]);
    }
}

// ---------------- kernel 1: embedding gather + input projection (unchanged) ------
#define BPAD 20
__global__ __launch_bounds__(256) void k_embed_proj(
    const int* __restrict__ x, const float* __restrict__ emb)
{
    __shared__ float a2[16][132];
    __shared__ float bsh[16 * 16 * BPAD];

    int tid = threadIdx.x;
    int jb  = blockIdx.x * 256;
    int by  = blockIdx.y;

    int arow  = tid & 63;
    int ahalf = tid >> 6;
    long tok  = x[by * 64 + arow];
    const float* erow = emb + (size_t)tok * EMB + ahalf * 4;

    int mg = tid >> 4;
    int cg = tid & 15;

    ull acc[32];
    {
        float4 b0 = *(const float4*)(g_br + jb + cg * 16);
        float4 b1 = *(const float4*)(g_br + jb + cg * 16 + 4);
        float4 b2 = *(const float4*)(g_br + jb + cg * 16 + 8);
        float4 b3 = *(const float4*)(g_br + jb + cg * 16 + 12);
        ull p[8] = { pk2(b0.x, b0.y), pk2(b0.z, b0.w), pk2(b1.x, b1.y), pk2(b1.z, b1.w),
                     pk2(b2.x, b2.y), pk2(b2.z, b2.w), pk2(b3.x, b3.y), pk2(b3.z, b3.w) };
#pragma unroll
        for (int m = 0; m < 4; m++)
#pragma unroll
            for (int q = 0; q < 8; q++) acc[m * 8 + q] = p[q];
    }

    float4 va;
    float4 rb[4];
#define E_LOAD(KB)                                                               \
    va = *(const float4*)(erow + (KB));                                         \
    _Pragma("unroll")                                                            \
    for (int i_ = 0; i_ < 4; i_++) {                                             \
        int f_ = tid + i_ * 256; int r_ = f_ >> 6, q_ = f_ & 63;                 \
        rb[i_] = *(const float4*)&g_Wr[(size_t)(HID + (KB) + r_) * NC + jb + q_ * 4]; \
    }

    E_LOAD(0)

    for (int kb = 0; kb < EMB; kb += 16) {
        __syncthreads();
        {
            int k0 = ahalf * 4;
            *(float2*)&a2[k0 + 0][2 * arow] = make_float2(va.x, va.x);
            *(float2*)&a2[k0 + 1][2 * arow] = make_float2(va.y, va.y);
            *(float2*)&a2[k0 + 2][2 * arow] = make_float2(va.z, va.z);
            *(float2*)&a2[k0 + 3][2 * arow] = make_float2(va.w, va.w);
        }
#pragma unroll
        for (int i_ = 0; i_ < 4; i_++) {
            int f_ = tid + i_ * 256; int r_ = f_ >> 6, q_ = f_ & 63;
            *(float4*)&bsh[r_ * (16 * BPAD) + (q_ >> 2) * BPAD + (q_ & 3) * 4] = rb[i_];
        }
        __syncthreads();
        if (kb + 16 < EMB) { E_LOAD(kb + 16) }

        const float* bp = &bsh[cg * BPAD];
#pragma unroll
        for (int k = 0; k < 16; k++) {
            ulonglong2 aa0 = *(const ulonglong2*)&a2[k][8 * mg];
            ulonglong2 aa1 = *(const ulonglong2*)&a2[k][8 * mg + 4];
            ulonglong2 bb0 = *(const ulonglong2*)(bp + k * (16 * BPAD));
            ulonglong2 bb1 = *(const ulonglong2*)(bp + k * (16 * BPAD) + 4);
            ulonglong2 bb2 = *(const ulonglong2*)(bp + k * (16 * BPAD) + 8);
            ulonglong2 bb3 = *(const ulonglong2*)(bp + k * (16 * BPAD) + 12);
            ull am[4] = { aa0.x, aa0.y, aa1.x, aa1.y };
            ull bq[8] = { bb0.x, bb0.y, bb1.x, bb1.y, bb2.x, bb2.y, bb3.x, bb3.y };
#pragma unroll
            for (int m = 0; m < 4; m++)
#pragma unroll
                for (int q = 0; q < 8; q++) fma2(acc[m * 8 + q], am[m], bq[q]);
        }
    }
#undef E_LOAD

#pragma unroll
    for (int m = 0; m < 4; m++) {
        float* op = g_xproj + (size_t)(by * 64 + mg * 4 + m) * NC + jb + cg * 16;
        float l0, h0, l1, h1;
#pragma unroll
        for (int q = 0; q < 4; q++) {
            up2(acc[m * 8 + 2 * q], l0, h0);
            up2(acc[m * 8 + 2 * q + 1], l1, h1);
            *(float4*)(op + q * 4) = make_float4(l0, h0, l1, h1);
        }
    }
}

// ---------------- kernel 2: PERSISTENT LSTM via mma.sync bf16 3-pass -------------
// 128 CTAs x 512 threads, 1 CTA/SM. CTA: 8 hidden units = N=32 interleaved cols.
// D[64,32] = h[64,1024] @ Wslice^T; 16 warps = 4 m-tiles x 4 n-tiles (m16n8 each).
// bf16 hi/lo splits, 3 MMA per k16 (AhBh + AlBh + AhBl), fp32 accum in registers.
// smem bytes: B persistent [split][32 rows][1024k] bf16 = 131072
//             A stream     [2 bufs][split][64 rows][128k] bf16 = 65536
//             D staging aliases A buf0 (64 x 36 fp32 = 9216)
#define OFF_A_B  131072
#define SMEM_LSTM (OFF_A_B + 65536)   // 192 KB

__global__ __launch_bounds__(512) void k_lstm(float* __restrict__ out)
{
    extern __shared__ __align__(16) float sm[];
    const uint32_t smb = su32(sm);

    int tid  = threadIdx.x;
    int lane = tid & 31, wid = tid >> 5;
    int j0   = blockIdx.x * 8;        // hidden units j0..j0+7
    int C0   = j0 * 4;                // interleaved col base (32 cols)

    // ---- startup: persistent B tiles (W slice bf16 hi/lo), XOR-swizzled ----
    // [split s][row c 0..31][unit q 0..127]; swz: low 3 bits of q ^= (c & 7)
#pragma unroll
    for (int i = 0; i < 16; i++) {
        int u = tid + i * 512;        // 0..8191 16B-units
        int s  = u >> 12;
        int rm = u & 4095;
        int c  = rm >> 7;
        int q  = rm & 127;
        int qp = (q & 0x78) | ((q ^ c) & 7);
        *(uint4*)((char*)sm + s * 65536 + c * 2048 + qp * 16) =
            *(const uint4*)&g_WT[s][C0 + c][q * 8];
    }
    __syncthreads();

    // warp tile assignment
    int mt = wid >> 2;                // 0..3 (m-tile of 16 rows)
    int nt = wid & 3;                 // 0..3 (n-tile of 8 cols)
    int rA = mt * 16 + (lane & 15);   // A ldmatrix row for this lane
    int khalf = lane >> 4;            // 0/1 -> k 0-7 / 8-15 halves
    int rB = nt * 8 + (lane & 7);     // B ldmatrix row (n) for this lane
    int kb = (lane >> 3) & 1;         // 0/1 -> B k half

    // gate-phase mapping: m = tid&63, unit u2 = tid>>6 (exactly 64 x 8 = 512)
    int m  = tid & 63;
    int u2 = tid >> 6;
    float c_reg = 0.f;

    // A-chunk loader: chunk = k128; 2048 16B-units / 512 thr = 4 each
#define A_LOAD(BUF, CH, PING) do {                                               \
    _Pragma("unroll")                                                            \
    for (int i_ = 0; i_ < 4; i_++) {                                             \
        int u_ = tid + i_ * 512;                                                 \
        int s_ = u_ >> 10, rm_ = u_ & 1023;                                      \
        int m_ = rm_ >> 4, q_ = rm_ & 15;                                        \
        int qp_ = (q_ & 8) | ((q_ ^ m_) & 7);                                    \
        cpa16(smb + OFF_A_B + (BUF) * 32768 + s_ * 16384 + m_ * 256 + qp_ * 16,  \
              &g_hbf[(PING)][s_][m_][(CH) * 128 + q_ * 8]);                      \
    }                                                                            \
    CP_COMMIT();                                                                 \
} while (0)

    for (int t = 0; t < L_SEQ; t++) {
        const int ping = t & 1, pnext = ping ^ 1;

        // prefetch this step's xproj early (consumed in gate phase)
        float4 xp = *(const float4*)&g_xproj[((size_t)t * 64 + m) * NC + C0 + u2 * 4];

        float d[4] = {0.f, 0.f, 0.f, 0.f};

        A_LOAD(0, 0, ping);
        for (int ch = 0; ch < 8; ch++) {
            int b = ch & 1;
            CP_WAIT0();               // chunk ch resident in buf b
            __syncthreads();          // all warps past chunk ch-1 (buf b^1 free)
            if (ch < 7) A_LOAD(b ^ 1, ch + 1, ping);

            uint32_t baseAh = smb + OFF_A_B + b * 32768 + rA * 256;          // split0
            uint32_t baseAl = baseAh + 16384;                                 // split1
            uint32_t baseBh = smb + rB * 2048;                                // split0
            uint32_t baseBl = baseBh + 65536;                                 // split1
            int kg0 = ch * 8;
#pragma unroll
            for (int ks = 0; ks < 8; ks++) {
                unsigned ah[4], al[4], bh[2], bl[2];
                int u  = ks * 2 + khalf;
                int up = (u & 8) | ((u ^ rA) & 7);
                ldsm_x4(ah, baseAh + up * 16);
                ldsm_x4(al, baseAl + up * 16);
                int qb = (kg0 + ks) * 2 + kb;
                int qp = (qb & 0x78) | ((qb ^ rB) & 7);
                ldsm_x2(bh, baseBh + qp * 16);
                ldsm_x2(bl, baseBl + qp * 16);
                mma_bf16(d, ah, bh);
                mma_bf16(d, al, bh);
                mma_bf16(d, ah, bl);
            }
        }

        // ---- stage D to smem (aliases A buf0; stride 36 floats) ----
        __syncthreads();              // all warps done reading A buffers
        float* Ds = sm + (OFF_A_B / 4);
        {
            int gid = lane >> 2, tig = lane & 3;
            int col = nt * 8 + tig * 2;
            *(float2*)&Ds[(mt * 16 + gid) * 36 + col]     = make_float2(d[0], d[1]);
            *(float2*)&Ds[(mt * 16 + gid + 8) * 36 + col] = make_float2(d[2], d[3]);
        }
        __syncthreads();

        // ---- gates: thread -> (m, j0+u2) ----
        float4 pv = *(const float4*)&Ds[m * 36 + u2 * 4];
        float pi = pv.x + xp.x;
        float pf = pv.y + xp.y;
        float pc = pv.z + xp.z;
        float po = pv.w + xp.w;
        float cn = sigm_f(pf) * c_reg + sigm_f(pi) * tanh_f(pc);
        c_reg = cn;
        float hv = sigm_f(po) * tanh_f(cn);

        int j = j0 + u2;
        out[((size_t)t * 64 + m) * 1024 + j] = hv;
        __nv_bfloat16 hh = __float2bfloat16(hv);
        __nv_bfloat16 hl = __float2bfloat16(hv - __bfloat162float(hh));
        g_hbf[pnext][0][m][j] = hh;
        g_hbf[pnext][1][m][j] = hl;

        // ---- software grid barrier (all 128 CTAs resident: 1 CTA/SM) ----
        __syncthreads();
        if (tid == 0) {
            bar_arrive_release(&g_bar);
            unsigned target = (unsigned)(t + 1) * NCTAS;
            while (ld_acquire(&g_bar) < target) { }
        }
        __syncthreads();
    }
#undef A_LOAD
}

// ---------------- launcher ----------------
extern "C" void kernel_launch(void* const* d_in, const int* in_sizes, int n_in,
                              void* d_out, int out_size)
{
    const int*   x   = (const int*)  d_in[0];
    const float* emb = (const float*)d_in[1];
    const float* Wi  = (const float*)d_in[2];
    const float* bi  = (const float*)d_in[3];
    const float* Wf  = (const float*)d_in[4];
    const float* bf  = (const float*)d_in[5];
    const float* Wc  = (const float*)d_in[6];
    const float* bc  = (const float*)d_in[7];
    const float* Wo  = (const float*)d_in[8];
    const float* bo  = (const float*)d_in[9];
    float* out = (float*)d_out;
    (void)in_sizes; (void)n_in; (void)out_size;

    static bool attr_done = false;
    if (!attr_done) {
        cudaFuncSetAttribute(k_lstm, cudaFuncAttributeMaxDynamicSharedMemorySize,
                             SMEM_LSTM);
        attr_done = true;
    }

    k_init<<<256, 256>>>();
    k_reorg<<<((HID + EMB) * HID + 255) / 256, 256>>>(Wi, bi, Wf, bf, Wc, bc, Wo, bo);

    dim3 g1(16, 512);
    k_embed_proj<<<g1, 256>>>(x, emb);

    k_lstm<<<NCTAS, 512, SMEM_LSTM>>>(out);
}